// round 8
// baseline (speedup 1.0000x reference)
#include <cuda_runtime.h>
#include <cuda_bf16.h>
#include <stdint.h>

#define B_     2
#define N_     65536
#define M_     16384
#define K_     32
#define KP_    15
#define DIN_   64
#define DOUT_  128
#define KTOT   960           // KP_*DIN_
#define SHADOW (-1000.0f)

// ---------------------------------------------------------------------------
// Scratch (__device__ globals per no-allocation rule)
// ---------------------------------------------------------------------------
__device__ float g_featT[(size_t)B_ * N_ * DIN_];                       // 33.5 MB
__device__ __align__(16) __nv_bfloat16 g_whi[(size_t)B_ * M_ * KTOT];   // 60 MB
__device__ __align__(16) __nv_bfloat16 g_wlo[(size_t)B_ * M_ * KTOT];   // 60 MB
__device__ __align__(16) __nv_bfloat16 g_bhi[DOUT_ * KTOT];             // W^T hi
__device__ __align__(16) __nv_bfloat16 g_blo[DOUT_ * KTOT];             // W^T lo

// ---------------------------------------------------------------------------
// helpers
// ---------------------------------------------------------------------------
__device__ __forceinline__ uint32_t smem_u32(const void* p) {
    uint32_t a;
    asm("{ .reg .u64 t; cvta.to.shared.u64 t, %1; cvt.u32.u64 %0, t; }"
        : "=r"(a) : "l"(p));
    return a;
}
__device__ __forceinline__ void ldsm4(uint32_t& r0, uint32_t& r1,
                                      uint32_t& r2, uint32_t& r3, uint32_t addr) {
    asm volatile("ldmatrix.sync.aligned.m8n8.x4.shared.b16 {%0,%1,%2,%3}, [%4];"
                 : "=r"(r0), "=r"(r1), "=r"(r2), "=r"(r3) : "r"(addr));
}
__device__ __forceinline__ void mma16816(float* c, const uint32_t* a,
                                         const uint32_t* b) {
    asm volatile("mma.sync.aligned.m16n8k16.row.col.f32.bf16.bf16.f32 "
                 "{%0,%1,%2,%3}, {%4,%5,%6,%7}, {%8,%9}, {%0,%1,%2,%3};"
                 : "+f"(c[0]), "+f"(c[1]), "+f"(c[2]), "+f"(c[3])
                 : "r"(a[0]), "r"(a[1]), "r"(a[2]), "r"(a[3]),
                   "r"(b[0]), "r"(b[1]));
}
__device__ __forceinline__ void cpasync16(uint32_t dst, const void* src) {
    asm volatile("cp.async.ca.shared.global [%0], [%1], 16;" :: "r"(dst), "l"(src));
}
__device__ __forceinline__ void cp_commit() {
    asm volatile("cp.async.commit_group;" ::: "memory");
}
__device__ __forceinline__ void cp_wait3() {
    asm volatile("cp.async.wait_group 3;" ::: "memory");
}
__device__ __forceinline__ void cp_wait2() {
    asm volatile("cp.async.wait_group 2;" ::: "memory");
}
__device__ __forceinline__ void cp_wait1() {
    asm volatile("cp.async.wait_group 1;" ::: "memory");
}
__device__ __forceinline__ void cp_wait0() {
    asm volatile("cp.async.wait_group 0;" ::: "memory");
}
// packed fp32x2 (Blackwell): doubles fp32 FMA throughput vs scalar FFMA
__device__ __forceinline__ unsigned long long pk2(float a, float b) {
    unsigned long long r;
    asm("mov.b64 %0, {%1, %2};" : "=l"(r) : "f"(a), "f"(b));
    return r;
}
__device__ __forceinline__ void fma2(unsigned long long& c,
                                     unsigned long long a, unsigned long long b) {
    asm("fma.rn.f32x2 %0, %1, %2, %0;" : "+l"(c) : "l"(a), "l"(b));
}
__device__ __forceinline__ void upk2(unsigned long long v, float& a, float& b) {
    asm("mov.b64 {%0, %1}, %2;" : "=f"(a), "=f"(b) : "l"(v));
}

// ---------------------------------------------------------------------------
// Kernel 1: transpose features [B][Din][N] -> g_featT [B][N][Din]
// ---------------------------------------------------------------------------
__global__ void transpose_feat_kernel(const float* __restrict__ f)
{
    __shared__ float tile[32][33];
    const int b  = blockIdx.z;
    const int n0 = blockIdx.x * 32;
    const int d0 = blockIdx.y * 32;
    const int x = threadIdx.x, y = threadIdx.y;

    #pragma unroll
    for (int i = y; i < 32; i += 8)
        tile[i][x] = f[((size_t)b * DIN_ + (d0 + i)) * N_ + n0 + x];
    __syncthreads();
    #pragma unroll
    for (int i = y; i < 32; i += 8)
        g_featT[((size_t)b * N_ + (n0 + i)) * DIN_ + d0 + x] = tile[x][i];
}

// ---------------------------------------------------------------------------
// Kernel 1b: weights [Kp][Din][Dout] -> g_bhi/g_blo [Dout rows][KTOT cols]
// ---------------------------------------------------------------------------
__global__ void prep_w_kernel(const float* __restrict__ w)
{
    const int e = blockIdx.x * 256 + threadIdx.x;
    if (e >= KP_ * DIN_ * DOUT_) return;
    const int kp = e / DOUT_, o = e % DOUT_;
    const float v = w[e];
    const __nv_bfloat16 hi = __float2bfloat16(v);
    const __nv_bfloat16 lo = __float2bfloat16(v - __bfloat162float(hi));
    g_bhi[o * KTOT + kp] = hi;
    g_blo[o * KTOT + kp] = lo;
}

// ---------------------------------------------------------------------------
// Kernel 2: 16 points per CTA, 512 threads.
//   Invalid (shadow) neighbors: index clamped to 0, w forced to 0 (shadow
//   feats are zero, so the contribution is zero either way) -> unconditional
//   gather loads, full MLP.
//   Phase 3 uses fma.rn.f32x2 (packed fp32) -> half the FMA-pipe pressure.
// NOTE: neighbor_indices is int32 (JAX canonicalizes int64 -> int32).
// ---------------------------------------------------------------------------
#define PTS 16
__global__ __launch_bounds__(512)
void kpconv_weighted_kernel(const float* __restrict__ points_xyz,
                            const float* __restrict__ center_xyz,
                            const int* __restrict__ nidx,
                            const float* __restrict__ kernel_points)
{
    const int bm0  = blockIdx.x * PTS;
    const int b    = bm0 >> 14;         // 16 | 16384 -> one batch per block
    const int t    = threadIdx.x;
    const int pt   = t >> 5;            // warp id == point id
    const int lane = t & 31;
    const int bm   = bm0 + pt;

    __shared__ int   s_idx[PTS][K_];    // clamped indices
    __shared__ float s_w[PTS][481];     // [pt][k*15+p] (+1 guard col)
    __shared__ float s_kp[KP_ * 3];

    if (t < KP_ * 3) s_kp[t] = kernel_points[t];

    // ---- phase 1: one (pt, k) per thread; coords stay in registers
    const int ii0 = nidx[(size_t)bm * K_ + lane];
    const bool valid = (unsigned)ii0 < (unsigned)N_;
    s_idx[pt][lane] = valid ? ii0 : 0;
    float px = SHADOW, py = SHADOW, pz = SHADOW;
    if (valid) {
        const float* pp = points_xyz + ((size_t)b * N_ + ii0) * 3;
        px = pp[0]; py = pp[1]; pz = pp[2];
    }
    const float rx = px - center_xyz[bm * 3 + 0];
    const float ry = py - center_xyz[bm * 3 + 1];
    const float rz = pz - center_xyz[bm * 3 + 2];
    float md = sqrtf(rx * rx + ry * ry + rz * rz);
    #pragma unroll
    for (int o = 16; o; o >>= 1)
        md = fmaxf(md, __shfl_xor_sync(0xffffffffu, md, o));
    const float inv = 1.0f / (md / 2.1f + 1e-5f);

    __syncthreads();                    // s_kp visible

    // ---- phase 2: w[pt][k=lane][p]; zero for shadow rows
    #pragma unroll
    for (int p = 0; p < KP_; ++p) {
        const float dx = rx - s_kp[p * 3 + 0] * md;
        const float dy = ry - s_kp[p * 3 + 1] * md;
        const float dz = rz - s_kp[p * 3 + 2] * md;
        float w = 1.0f - sqrtf(dx * dx + dy * dy + dz * dz) * inv;
        w = fmaxf(w, 0.0f);
        s_w[pt][lane * 15 + p] = valid ? w : 0.0f;
    }
    __syncthreads();

    // ---- phase 3: packed f32x2 accumulate of weighted[p][d]
    const int d4 = lane >> 1, ph = lane & 1;
    const int pbase = ph * 8;
    unsigned long long accp[8][2];
    #pragma unroll
    for (int j = 0; j < 8; ++j) { accp[j][0] = 0ull; accp[j][1] = 0ull; }

    const float* wrow = s_w[pt];
    const float* fbase = g_featT + (size_t)b * N_ * DIN_ + d4 * 4;
    #pragma unroll 4
    for (int k = 0; k < K_; ++k) {
        const float4 f = *(const float4*)(fbase + (size_t)s_idx[pt][k] * DIN_);
        const unsigned long long f01 = pk2(f.x, f.y);
        const unsigned long long f23 = pk2(f.z, f.w);
        #pragma unroll
        for (int j = 0; j < 8; ++j) {
            // ph=1, j=7 reads wrow[k*15+15] (guard col, result unused)
            const float wv = wrow[k * 15 + pbase + j];
            const unsigned long long wp = pk2(wv, wv);
            fma2(accp[j][0], wp, f01);
            fma2(accp[j][1], wp, f23);
        }
    }

    // ---- phase 4: bf16 hi/lo split, coalesced 8B stores
    const size_t rowOff = (size_t)bm * KTOT + d4 * 4;
    const int np = 8 - ph;              // ph=1 owns only p=8..14
    #pragma unroll
    for (int j = 0; j < 8; ++j) {
        if (j < np) {
            const int p = pbase + j;
            float a[4];
            upk2(accp[j][0], a[0], a[1]);
            upk2(accp[j][1], a[2], a[3]);
            __nv_bfloat16 h[4], l[4];
            #pragma unroll
            for (int q = 0; q < 4; ++q) {
                h[q] = __float2bfloat16(a[q]);
                l[q] = __float2bfloat16(a[q] - __bfloat162float(h[q]));
            }
            *(uint2*)&g_whi[rowOff + p * DIN_] = *(const uint2*)h;
            *(uint2*)&g_wlo[rowOff + p * DIN_] = *(const uint2*)l;
        }
    }
}

// ---------------------------------------------------------------------------
// Kernel 3: mma.sync bf16 GEMM, 3-term hi/lo split, cp.async 4-stage pipeline
//   C[128x128] per CTA = A[128x960] @ W[960x128]; BK=32, 30 chunks
// ---------------------------------------------------------------------------
#define BK    32
#define NCHUNK (KTOT / BK)       // 30
#define LDS_  40                 // row stride (elements): 80B, ldsm conflict-free
#define ARR_BYTES  (128 * LDS_ * 2)          // 10240 B per array
#define STAGE_BYTES (4 * ARR_BYTES)          // Ah, Al, Bh, Bl = 40960 B
#define NSTAGE 4
#define GEMM_SMEM  (NSTAGE * STAGE_BYTES)    // 163840 B

__global__ __launch_bounds__(256)
void kpconv_mma_gemm(float* __restrict__ out)
{
    extern __shared__ __align__(16) char sm[];
    const uint32_t smem_base = smem_u32(sm);

    const int tid  = threadIdx.x;
    const int wid  = tid >> 5, lane = tid & 31;
    const int wm   = wid & 3;        // warp m-offset: wm*32
    const int wn   = wid >> 2;       // warp n-offset: wn*64
    const size_t rowBase = (size_t)blockIdx.x * 128;

    auto issue_chunk = [&](int c, int stage) {
        const uint32_t sb = smem_base + stage * STAGE_BYTES;
        #pragma unroll
        for (int i = 0; i < 8; ++i) {
            const int idx = tid + i * 256;
            const int arr = idx >> 9;           // 0..3
            const int rem = idx & 511;
            const int row = rem >> 2, seg = rem & 3;
            const uint32_t dst = sb + arr * ARR_BYTES + (row * LDS_ + seg * 8) * 2;
            const __nv_bfloat16* src;
            if (arr == 0)      src = g_whi + (rowBase + row) * KTOT + c * BK + seg * 8;
            else if (arr == 1) src = g_wlo + (rowBase + row) * KTOT + c * BK + seg * 8;
            else if (arr == 2) src = g_bhi + (size_t)row * KTOT + c * BK + seg * 8;
            else               src = g_blo + (size_t)row * KTOT + c * BK + seg * 8;
            cpasync16(dst, src);
        }
        cp_commit();
    };

    float acc[2][8][4];
    #pragma unroll
    for (int i = 0; i < 2; i++)
        #pragma unroll
        for (int j = 0; j < 8; j++)
            #pragma unroll
            for (int q = 0; q < 4; q++) acc[i][j][q] = 0.0f;

    // per-lane ldmatrix row/col patterns
    const int ltile = lane >> 3, lr = lane & 7;
    const int aRow = (ltile & 1) * 8 + lr;
    const int aCol = (ltile >> 1) * 8;
    const int bRow = (ltile >> 1) * 8 + lr;
    const int bCol = (ltile & 1) * 8;

    issue_chunk(0, 0);
    issue_chunk(1, 1);
    issue_chunk(2, 2);

    for (int c = 0; c < NCHUNK; ++c) {
        if (c + 3 < NCHUNK) issue_chunk(c + 3, (c + 3) & (NSTAGE - 1));
        const int remain = NCHUNK - 1 - c;
        if      (remain >= 3) cp_wait3();
        else if (remain == 2) cp_wait2();
        else if (remain == 1) cp_wait1();
        else                  cp_wait0();
        __syncthreads();

        const uint32_t sb  = smem_base + (c & (NSTAGE - 1)) * STAGE_BYTES;
        const uint32_t pAh = sb;
        const uint32_t pAl = sb + ARR_BYTES;
        const uint32_t pBh = sb + 2 * ARR_BYTES;
        const uint32_t pBl = sb + 3 * ARR_BYTES;

        #pragma unroll
        for (int kk = 0; kk < 2; ++kk) {
            const int kcol = kk * 16;
            uint32_t afh[2][4], afl[2][4];
            #pragma unroll
            for (int mt = 0; mt < 2; ++mt) {
                const int row = wm * 32 + mt * 16 + aRow;
                const int col = kcol + aCol;
                const uint32_t off = (uint32_t)(row * LDS_ + col) * 2;
                ldsm4(afh[mt][0], afh[mt][1], afh[mt][2], afh[mt][3], pAh + off);
                ldsm4(afl[mt][0], afl[mt][1], afl[mt][2], afl[mt][3], pAl + off);
            }
            #pragma unroll
            for (int g = 0; g < 4; ++g) {
                const int row = wn * 64 + g * 16 + bRow;
                const int col = kcol + bCol;
                const uint32_t off = (uint32_t)(row * LDS_ + col) * 2;
                uint32_t bh[4], bl[4];
                ldsm4(bh[0], bh[1], bh[2], bh[3], pBh + off);
                ldsm4(bl[0], bl[1], bl[2], bl[3], pBl + off);
                #pragma unroll
                for (int half = 0; half < 2; ++half) {
                    const int nt = 2 * g + half;
                    #pragma unroll
                    for (int mt = 0; mt < 2; ++mt) {
                        mma16816(acc[mt][nt], afh[mt], bh + 2 * half);
                        mma16816(acc[mt][nt], afl[mt], bh + 2 * half);
                        mma16816(acc[mt][nt], afh[mt], bl + 2 * half);
                    }
                }
            }
        }
        __syncthreads();
    }

    // epilogue: c0:(r,c) c1:(r,c+1) c2:(r+8,c) c3:(r+8,c+1)
    const int bb     = (int)(rowBase >> 14);
    const int mLocal = (int)(rowBase & 16383);
    #pragma unroll
    for (int mt = 0; mt < 2; ++mt)
        #pragma unroll
        for (int nt = 0; nt < 8; ++nt) {
            const int m0 = mLocal + wm * 32 + mt * 16 + (lane >> 2);
            const int n0 = wn * 64 + nt * 8 + 2 * (lane & 3);
            float* o0 = out + ((size_t)bb * DOUT_ + n0) * M_ + m0;
            o0[0]      = acc[mt][nt][0];
            o0[M_]     = acc[mt][nt][1];
            o0[8]      = acc[mt][nt][2];
            o0[M_ + 8] = acc[mt][nt][3];
        }
}

// ---------------------------------------------------------------------------
extern "C" void kernel_launch(void* const* d_in, const int* in_sizes, int n_in,
                              void* d_out, int out_size)
{
    // Dispatch inputs by (pairwise-distinct) element count:
    const float* points_xyz    = nullptr;
    const float* features      = nullptr;
    const float* center_xyz    = nullptr;
    const int*   neighbor_idx  = nullptr;
    const float* kernel_points = nullptr;
    const float* weights       = nullptr;

    for (int i = 0; i < n_in; i++) {
        switch (in_sizes[i]) {
            case 393216:  points_xyz    = (const float*)d_in[i]; break;
            case 8388608: features      = (const float*)d_in[i]; break;
            case 98304:   center_xyz    = (const float*)d_in[i]; break;
            case 1048576: neighbor_idx  = (const int*)d_in[i];   break;
            case 45:      kernel_points = (const float*)d_in[i]; break;
            case 122880:  weights       = (const float*)d_in[i]; break;
            default: break;
        }
    }
    float* out = (float*)d_out;

    cudaFuncSetAttribute(kpconv_mma_gemm,
                         cudaFuncAttributeMaxDynamicSharedMemorySize, GEMM_SMEM);
    cudaFuncSetAttribute(kpconv_mma_gemm,
                         cudaFuncAttributePreferredSharedMemoryCarveout, 100);

    dim3 g1(N_ / 32, DIN_ / 32, B_);
    transpose_feat_kernel<<<g1, dim3(32, 8)>>>(features);

    prep_w_kernel<<<(KP_ * DIN_ * DOUT_ + 255) / 256, 256>>>(weights);

    kpconv_weighted_kernel<<<(B_ * M_) / PTS, 512>>>(points_xyz, center_xyz,
                                                     neighbor_idx, kernel_points);

    kpconv_mma_gemm<<<(B_ * M_) / 128, 256, GEMM_SMEM>>>(out);
}

// round 9
// speedup vs baseline: 1.0227x; 1.0227x over previous
#include <cuda_runtime.h>
#include <cuda_bf16.h>
#include <stdint.h>

#define B_     2
#define N_     65536
#define M_     16384
#define K_     32
#define KP_    15
#define DIN_   64
#define DOUT_  128
#define KTOT   960           // KP_*DIN_
#define SHADOW (-1000.0f)

// ---------------------------------------------------------------------------
// Scratch (__device__ globals per no-allocation rule)
// ---------------------------------------------------------------------------
__device__ float g_featT[(size_t)B_ * N_ * DIN_];                       // 33.5 MB
__device__ __align__(16) __nv_bfloat16 g_whi[(size_t)B_ * M_ * KTOT];   // 60 MB
__device__ __align__(16) __nv_bfloat16 g_wlo[(size_t)B_ * M_ * KTOT];   // 60 MB
__device__ __align__(16) __nv_bfloat16 g_bhi[DOUT_ * KTOT];             // W^T hi
__device__ __align__(16) __nv_bfloat16 g_blo[DOUT_ * KTOT];             // W^T lo

// ---------------------------------------------------------------------------
// helpers
// ---------------------------------------------------------------------------
__device__ __forceinline__ uint32_t smem_u32(const void* p) {
    uint32_t a;
    asm("{ .reg .u64 t; cvta.to.shared.u64 t, %1; cvt.u32.u64 %0, t; }"
        : "=r"(a) : "l"(p));
    return a;
}
__device__ __forceinline__ void ldsm4(uint32_t& r0, uint32_t& r1,
                                      uint32_t& r2, uint32_t& r3, uint32_t addr) {
    asm volatile("ldmatrix.sync.aligned.m8n8.x4.shared.b16 {%0,%1,%2,%3}, [%4];"
                 : "=r"(r0), "=r"(r1), "=r"(r2), "=r"(r3) : "r"(addr));
}
__device__ __forceinline__ void ldsm4t(uint32_t& r0, uint32_t& r1,
                                       uint32_t& r2, uint32_t& r3, uint32_t addr) {
    asm volatile("ldmatrix.sync.aligned.m8n8.x4.trans.shared.b16 {%0,%1,%2,%3}, [%4];"
                 : "=r"(r0), "=r"(r1), "=r"(r2), "=r"(r3) : "r"(addr));
}
__device__ __forceinline__ void mma16816(float* c, const uint32_t* a,
                                         const uint32_t* b) {
    asm volatile("mma.sync.aligned.m16n8k16.row.col.f32.bf16.bf16.f32 "
                 "{%0,%1,%2,%3}, {%4,%5,%6,%7}, {%8,%9}, {%0,%1,%2,%3};"
                 : "+f"(c[0]), "+f"(c[1]), "+f"(c[2]), "+f"(c[3])
                 : "r"(a[0]), "r"(a[1]), "r"(a[2]), "r"(a[3]),
                   "r"(b[0]), "r"(b[1]));
}
__device__ __forceinline__ void cpasync16(uint32_t dst, const void* src) {
    asm volatile("cp.async.ca.shared.global [%0], [%1], 16;" :: "r"(dst), "l"(src));
}
__device__ __forceinline__ void cp_commit() {
    asm volatile("cp.async.commit_group;" ::: "memory");
}
__device__ __forceinline__ void cp_wait1() {
    asm volatile("cp.async.wait_group 1;" ::: "memory");
}
__device__ __forceinline__ void cp_wait0() {
    asm volatile("cp.async.wait_group 0;" ::: "memory");
}
// pack two floats -> bf16x2 word (a in low half); and residual helper
__device__ __forceinline__ uint32_t pkbf2(float a, float b) {
    __nv_bfloat162 t = __floats2bfloat162_rn(a, b);
    return *(uint32_t*)&t;
}

// ---------------------------------------------------------------------------
// Kernel 1: transpose features [B][Din][N] -> g_featT [B][N][Din]
// ---------------------------------------------------------------------------
__global__ void transpose_feat_kernel(const float* __restrict__ f)
{
    __shared__ float tile[32][33];
    const int b  = blockIdx.z;
    const int n0 = blockIdx.x * 32;
    const int d0 = blockIdx.y * 32;
    const int x = threadIdx.x, y = threadIdx.y;

    #pragma unroll
    for (int i = y; i < 32; i += 8)
        tile[i][x] = f[((size_t)b * DIN_ + (d0 + i)) * N_ + n0 + x];
    __syncthreads();
    #pragma unroll
    for (int i = y; i < 32; i += 8)
        g_featT[((size_t)b * N_ + (n0 + i)) * DIN_ + d0 + x] = tile[x][i];
}

// ---------------------------------------------------------------------------
// Kernel 1b: weights [Kp][Din][Dout] -> g_bhi/g_blo [Dout rows][KTOT cols]
// ---------------------------------------------------------------------------
__global__ void prep_w_kernel(const float* __restrict__ w)
{
    const int e = blockIdx.x * 256 + threadIdx.x;
    if (e >= KP_ * DIN_ * DOUT_) return;
    const int kp = e / DOUT_, o = e % DOUT_;
    const float v = w[e];
    const __nv_bfloat16 hi = __float2bfloat16(v);
    const __nv_bfloat16 lo = __float2bfloat16(v - __bfloat162float(hi));
    g_bhi[o * KTOT + kp] = hi;
    g_blo[o * KTOT + kp] = lo;
}

// ---------------------------------------------------------------------------
// Kernel 2: einsum1 on tensor cores. warp <-> point; 8 points per 256-thr CTA.
//   weighted[p][d] = sum_k w[k][p] * feat[k][d]  ==  mma(M=16, N=64, K=32)
//   A = w^T [16 x 32] bf16 hi/lo (row 15 zero, shadow k -> w=0)
//   B = feat [32 x 64] bf16 hi/lo, k-major rows, ldmatrix.trans
//   3-term split: Ah*Bh + Al*Bh + Ah*Bl, fp32 acc; no __syncthreads needed.
// NOTE: neighbor_indices is int32 (JAX canonicalizes int64 -> int32).
// ---------------------------------------------------------------------------
#define PTS2   8
#define FSTR   72                        // feat smem row stride (elems)
#define WSTR   40                        // w smem row stride (elems)
#define F_BYTES (K_ * FSTR * 2)          // 4608
#define W_BYTES (16 * WSTR * 2)          // 1280
#define PT_BYTES (2 * F_BYTES + 2 * W_BYTES)   // 11776
#define K2_SMEM (PTS2 * PT_BYTES)        // 94208

__global__ __launch_bounds__(256)
void kpconv_weighted_mma(const float* __restrict__ points_xyz,
                         const float* __restrict__ center_xyz,
                         const int* __restrict__ nidx,
                         const float* __restrict__ kernel_points)
{
    extern __shared__ __align__(16) char k2sm[];
    const int wpt  = threadIdx.x >> 5;   // warp id == local point id
    const int lane = threadIdx.x & 31;
    const int bm   = blockIdx.x * PTS2 + wpt;
    const int b    = bm >> 14;

    __nv_bfloat16* sFh = (__nv_bfloat16*)(k2sm + wpt * PT_BYTES);
    __nv_bfloat16* sFl = sFh + K_ * FSTR;
    __nv_bfloat16* sWh = sFl + K_ * FSTR;
    __nv_bfloat16* sWl = sWh + 16 * WSTR;

    // ---- phase 1: lane = k; coords in registers
    const int ii0 = nidx[(size_t)bm * K_ + lane];
    const bool valid = (unsigned)ii0 < (unsigned)N_;
    const int idx = valid ? ii0 : 0;
    float px = SHADOW, py = SHADOW, pz = SHADOW;
    if (valid) {
        const float* pp = points_xyz + ((size_t)b * N_ + ii0) * 3;
        px = pp[0]; py = pp[1]; pz = pp[2];
    }
    const float rx = px - center_xyz[bm * 3 + 0];
    const float ry = py - center_xyz[bm * 3 + 1];
    const float rz = pz - center_xyz[bm * 3 + 2];
    float md = sqrtf(rx * rx + ry * ry + rz * rz);
    #pragma unroll
    for (int o = 16; o; o >>= 1)
        md = fmaxf(md, __shfl_xor_sync(0xffffffffu, md, o));
    const float inv = 1.0f / (md / 2.1f + 1e-5f);

    // ---- phase 2: w[p] -> A smem [p][k=lane], bf16 hi/lo; row 15 zero
    #pragma unroll
    for (int p = 0; p < KP_; ++p) {
        const float kx = kernel_points[p * 3 + 0] * md;
        const float ky = kernel_points[p * 3 + 1] * md;
        const float kz = kernel_points[p * 3 + 2] * md;
        const float dx = rx - kx, dy = ry - ky, dz = rz - kz;
        float w = 1.0f - sqrtf(dx * dx + dy * dy + dz * dz) * inv;
        w = valid ? fmaxf(w, 0.0f) : 0.0f;
        const __nv_bfloat16 h = __float2bfloat16(w);
        sWh[p * WSTR + lane] = h;
        sWl[p * WSTR + lane] = __float2bfloat16(w - __bfloat162float(h));
    }
    sWh[15 * WSTR + lane] = __float2bfloat16(0.0f);
    sWl[15 * WSTR + lane] = __float2bfloat16(0.0f);

    // ---- phase 3: gather feat row k=lane (64 f32), convert, store B smem
    {
        const float4* gf = (const float4*)(g_featT + ((size_t)b * N_ + idx) * DIN_);
        #pragma unroll
        for (int s = 0; s < 8; ++s) {           // 8 x (8 floats -> 16B hi + 16B lo)
            const float4 f0 = gf[s * 2 + 0];
            const float4 f1 = gf[s * 2 + 1];
            uint32_t h[4], l[4];
            h[0] = pkbf2(f0.x, f0.y); h[1] = pkbf2(f0.z, f0.w);
            h[2] = pkbf2(f1.x, f1.y); h[3] = pkbf2(f1.z, f1.w);
            const __nv_bfloat162* hh = (const __nv_bfloat162*)h;
            l[0] = pkbf2(f0.x - __bfloat162float(hh[0].x),
                         f0.y - __bfloat162float(hh[0].y));
            l[1] = pkbf2(f0.z - __bfloat162float(hh[1].x),
                         f0.w - __bfloat162float(hh[1].y));
            l[2] = pkbf2(f1.x - __bfloat162float(hh[2].x),
                         f1.y - __bfloat162float(hh[2].y));
            l[3] = pkbf2(f1.z - __bfloat162float(hh[3].x),
                         f1.w - __bfloat162float(hh[3].y));
            *(uint4*)&sFh[lane * FSTR + s * 8] = *(uint4*)h;
            *(uint4*)&sFl[lane * FSTR + s * 8] = *(uint4*)l;
        }
    }
    __syncwarp();

    // ---- phase 4: 48 mma (2 k-chunks x 4 ldsm-groups x 2 n-tiles x 3 terms)
    float acc[8][4];
    #pragma unroll
    for (int j = 0; j < 8; ++j)
        #pragma unroll
        for (int q = 0; q < 4; ++q) acc[j][q] = 0.0f;

    const int ltile = lane >> 3, lr = lane & 7;
    // A (no trans): tiles m0-7/k0, m8-15/k0, m0-7/k8, m8-15/k8
    const int aRow = (ltile & 1) * 8 + lr;
    const int aCol = (ltile >> 1) * 8;
    // B (trans): tiles k0/n0, k8/n0, k0/n8, k8/n8
    const int bRow = (ltile & 1) * 8 + lr;
    const int bCol = (ltile >> 1) * 8;

    #pragma unroll
    for (int kc = 0; kc < 2; ++kc) {
        uint32_t ah[4], al[4];
        const uint32_t aOff = (uint32_t)(aRow * WSTR + kc * 16 + aCol) * 2;
        ldsm4(ah[0], ah[1], ah[2], ah[3], smem_u32(sWh) + aOff);
        ldsm4(al[0], al[1], al[2], al[3], smem_u32(sWl) + aOff);
        #pragma unroll
        for (int g = 0; g < 4; ++g) {           // n in 16-wide groups
            const uint32_t bOff =
                (uint32_t)((kc * 16 + bRow) * FSTR + g * 16 + bCol) * 2;
            uint32_t bh[4], bl[4];
            ldsm4t(bh[0], bh[1], bh[2], bh[3], smem_u32(sFh) + bOff);
            ldsm4t(bl[0], bl[1], bl[2], bl[3], smem_u32(sFl) + bOff);
            #pragma unroll
            for (int half = 0; half < 2; ++half) {
                const int nt = 2 * g + half;
                mma16816(acc[nt], ah, bh + 2 * half);
                mma16816(acc[nt], al, bh + 2 * half);
                mma16816(acc[nt], ah, bl + 2 * half);
            }
        }
    }

    // ---- epilogue: c-frag (row=p, col=d) -> g_whi/g_wlo, skip p==15
    const int r  = lane >> 2;
    const int cb = 2 * (lane & 3);
    __nv_bfloat16* wh = g_whi + (size_t)bm * KTOT;
    __nv_bfloat16* wl = g_wlo + (size_t)bm * KTOT;
    #pragma unroll
    for (int nt = 0; nt < 8; ++nt) {
        const int d0 = nt * 8 + cb;
        {   // p = r (0..7)
            const uint32_t h01 = pkbf2(acc[nt][0], acc[nt][1]);
            const __nv_bfloat162* hp = (const __nv_bfloat162*)&h01;
            const uint32_t l01 = pkbf2(acc[nt][0] - __bfloat162float(hp->x),
                                       acc[nt][1] - __bfloat162float(hp->y));
            *(uint32_t*)(wh + r * DIN_ + d0) = h01;
            *(uint32_t*)(wl + r * DIN_ + d0) = l01;
        }
        if (r + 8 < KP_) {   // p = r+8 (8..14); p==15 would alias next point
            const uint32_t h23 = pkbf2(acc[nt][2], acc[nt][3]);
            const __nv_bfloat162* hp = (const __nv_bfloat162*)&h23;
            const uint32_t l23 = pkbf2(acc[nt][2] - __bfloat162float(hp->x),
                                       acc[nt][3] - __bfloat162float(hp->y));
            *(uint32_t*)(wh + (r + 8) * DIN_ + d0) = h23;
            *(uint32_t*)(wl + (r + 8) * DIN_ + d0) = l23;
        }
    }
}

// ---------------------------------------------------------------------------
// Kernel 3: mma.sync bf16 GEMM, 3-term hi/lo split, cp.async double buffer
//   (exact R6 configuration: 2 stages, no min-blocks clamp)
// ---------------------------------------------------------------------------
#define BK    32
#define LDS_  40                 // row stride (elements): 80B, ldsm conflict-free
#define ARR_BYTES  (128 * LDS_ * 2)          // 10240 B per array
#define STAGE_BYTES (4 * ARR_BYTES)          // Ah, Al, Bh, Bl
#define GEMM_SMEM  (2 * STAGE_BYTES)         // 81920 B

__global__ __launch_bounds__(256)
void kpconv_mma_gemm(float* __restrict__ out)
{
    extern __shared__ __align__(16) char sm[];
    const uint32_t smem_base = smem_u32(sm);

    const int tid  = threadIdx.x;
    const int wid  = tid >> 5, lane = tid & 31;
    const int wm   = wid & 3;        // warp m-offset: wm*32
    const int wn   = wid >> 2;       // warp n-offset: wn*64
    const size_t rowBase = (size_t)blockIdx.x * 128;

    auto issue_chunk = [&](int c, int stage) {
        const uint32_t sb = smem_base + stage * STAGE_BYTES;
        #pragma unroll
        for (int i = 0; i < 8; ++i) {
            const int idx = tid + i * 256;
            const int arr = idx >> 9;           // 0..3
            const int rem = idx & 511;
            const int row = rem >> 2, seg = rem & 3;
            const uint32_t dst = sb + arr * ARR_BYTES + (row * LDS_ + seg * 8) * 2;
            const __nv_bfloat16* src;
            if (arr == 0)      src = g_whi + (rowBase + row) * KTOT + c * BK + seg * 8;
            else if (arr == 1) src = g_wlo + (rowBase + row) * KTOT + c * BK + seg * 8;
            else if (arr == 2) src = g_bhi + (size_t)row * KTOT + c * BK + seg * 8;
            else               src = g_blo + (size_t)row * KTOT + c * BK + seg * 8;
            cpasync16(dst, src);
        }
        cp_commit();
    };

    float acc[2][8][4];
    #pragma unroll
    for (int i = 0; i < 2; i++)
        #pragma unroll
        for (int j = 0; j < 8; j++)
            #pragma unroll
            for (int q = 0; q < 4; q++) acc[i][j][q] = 0.0f;

    // per-lane ldmatrix row/col patterns
    const int ltile = lane >> 3, lr = lane & 7;
    const int aRow = (ltile & 1) * 8 + lr;
    const int aCol = (ltile >> 1) * 8;
    const int bRow = (ltile >> 1) * 8 + lr;
    const int bCol = (ltile & 1) * 8;

    issue_chunk(0, 0);

    for (int c = 0; c < KTOT / BK; ++c) {
        if (c + 1 < KTOT / BK) { issue_chunk(c + 1, (c + 1) & 1); cp_wait1(); }
        else                   { cp_wait0(); }
        __syncthreads();

        const uint32_t sb  = smem_base + (c & 1) * STAGE_BYTES;
        const uint32_t pAh = sb;
        const uint32_t pAl = sb + ARR_BYTES;
        const uint32_t pBh = sb + 2 * ARR_BYTES;
        const uint32_t pBl = sb + 3 * ARR_BYTES;

        #pragma unroll
        for (int kk = 0; kk < 2; ++kk) {
            const int kcol = kk * 16;
            uint32_t afh[2][4], afl[2][4];
            #pragma unroll
            for (int mt = 0; mt < 2; ++mt) {
                const int row = wm * 32 + mt * 16 + aRow;
                const int col = kcol + aCol;
                const uint32_t off = (uint32_t)(row * LDS_ + col) * 2;
                ldsm4(afh[mt][0], afh[mt][1], afh[mt][2], afh[mt][3], pAh + off);
                ldsm4(afl[mt][0], afl[mt][1], afl[mt][2], afl[mt][3], pAl + off);
            }
            #pragma unroll
            for (int g = 0; g < 4; ++g) {
                const int row = wn * 64 + g * 16 + bRow;
                const int col = kcol + bCol;
                const uint32_t off = (uint32_t)(row * LDS_ + col) * 2;
                uint32_t bh[4], bl[4];
                ldsm4(bh[0], bh[1], bh[2], bh[3], pBh + off);
                ldsm4(bl[0], bl[1], bl[2], bl[3], pBl + off);
                #pragma unroll
                for (int half = 0; half < 2; ++half) {
                    const int nt = 2 * g + half;
                    #pragma unroll
                    for (int mt = 0; mt < 2; ++mt) {
                        mma16816(acc[mt][nt], afh[mt], bh + 2 * half);
                        mma16816(acc[mt][nt], afl[mt], bh + 2 * half);
                        mma16816(acc[mt][nt], afh[mt], bl + 2 * half);
                    }
                }
            }
        }
        __syncthreads();
    }

    // epilogue: c0:(r,c) c1:(r,c+1) c2:(r+8,c) c3:(r+8,c+1)
    const int bb     = (int)(rowBase >> 14);
    const int mLocal = (int)(rowBase & 16383);
    #pragma unroll
    for (int mt = 0; mt < 2; ++mt)
        #pragma unroll
        for (int nt = 0; nt < 8; ++nt) {
            const int m0 = mLocal + wm * 32 + mt * 16 + (lane >> 2);
            const int n0 = wn * 64 + nt * 8 + 2 * (lane & 3);
            float* o0 = out + ((size_t)bb * DOUT_ + n0) * M_ + m0;
            o0[0]      = acc[mt][nt][0];
            o0[M_]     = acc[mt][nt][1];
            o0[8]      = acc[mt][nt][2];
            o0[M_ + 8] = acc[mt][nt][3];
        }
}

// ---------------------------------------------------------------------------
extern "C" void kernel_launch(void* const* d_in, const int* in_sizes, int n_in,
                              void* d_out, int out_size)
{
    // Dispatch inputs by (pairwise-distinct) element count:
    const float* points_xyz    = nullptr;
    const float* features      = nullptr;
    const float* center_xyz    = nullptr;
    const int*   neighbor_idx  = nullptr;
    const float* kernel_points = nullptr;
    const float* weights       = nullptr;

    for (int i = 0; i < n_in; i++) {
        switch (in_sizes[i]) {
            case 393216:  points_xyz    = (const float*)d_in[i]; break;
            case 8388608: features      = (const float*)d_in[i]; break;
            case 98304:   center_xyz    = (const float*)d_in[i]; break;
            case 1048576: neighbor_idx  = (const int*)d_in[i];   break;
            case 45:      kernel_points = (const float*)d_in[i]; break;
            case 122880:  weights       = (const float*)d_in[i]; break;
            default: break;
        }
    }
    float* out = (float*)d_out;

    cudaFuncSetAttribute(kpconv_mma_gemm,
                         cudaFuncAttributeMaxDynamicSharedMemorySize, GEMM_SMEM);
    cudaFuncSetAttribute(kpconv_weighted_mma,
                         cudaFuncAttributeMaxDynamicSharedMemorySize, K2_SMEM);

    dim3 g1(N_ / 32, DIN_ / 32, B_);
    transpose_feat_kernel<<<g1, dim3(32, 8)>>>(features);

    prep_w_kernel<<<(KP_ * DIN_ * DOUT_ + 255) / 256, 256>>>(weights);

    kpconv_weighted_mma<<<(B_ * M_) / PTS2, 256, K2_SMEM>>>(
        points_xyz, center_xyz, neighbor_idx, kernel_points);

    kpconv_mma_gemm<<<(B_ * M_) / 128, 256, GEMM_SMEM>>>(out);
}

// round 10
// speedup vs baseline: 1.1976x; 1.1710x over previous
#include <cuda_runtime.h>
#include <cuda_bf16.h>
#include <stdint.h>

#define B_     2
#define N_     65536
#define M_     16384
#define K_     32
#define KP_    15
#define DIN_   64
#define DOUT_  128
#define KTOT   960           // KP_*DIN_
#define SHADOW (-1000.0f)

// ---------------------------------------------------------------------------
// Scratch (__device__ globals per no-allocation rule)
// ---------------------------------------------------------------------------
__device__ float g_featT[(size_t)B_ * N_ * DIN_];                       // 33.5 MB
__device__ __align__(16) __nv_bfloat16 g_whi[(size_t)B_ * M_ * KTOT];   // 60 MB
__device__ __align__(16) __nv_bfloat16 g_wlo[(size_t)B_ * M_ * KTOT];   // 60 MB
__device__ __align__(16) __nv_bfloat16 g_bhi[DOUT_ * KTOT];             // W^T hi
__device__ __align__(16) __nv_bfloat16 g_blo[DOUT_ * KTOT];             // W^T lo

// ---------------------------------------------------------------------------
// helpers
// ---------------------------------------------------------------------------
__device__ __forceinline__ uint32_t smem_u32(const void* p) {
    uint32_t a;
    asm("{ .reg .u64 t; cvta.to.shared.u64 t, %1; cvt.u32.u64 %0, t; }"
        : "=r"(a) : "l"(p));
    return a;
}
__device__ __forceinline__ void ldsm4(uint32_t& r0, uint32_t& r1,
                                      uint32_t& r2, uint32_t& r3, uint32_t addr) {
    asm volatile("ldmatrix.sync.aligned.m8n8.x4.shared.b16 {%0,%1,%2,%3}, [%4];"
                 : "=r"(r0), "=r"(r1), "=r"(r2), "=r"(r3) : "r"(addr));
}
__device__ __forceinline__ void ldsm4t(uint32_t& r0, uint32_t& r1,
                                       uint32_t& r2, uint32_t& r3, uint32_t addr) {
    asm volatile("ldmatrix.sync.aligned.m8n8.x4.trans.shared.b16 {%0,%1,%2,%3}, [%4];"
                 : "=r"(r0), "=r"(r1), "=r"(r2), "=r"(r3) : "r"(addr));
}
__device__ __forceinline__ void mma16816(float* c, const uint32_t* a,
                                         const uint32_t* b) {
    asm volatile("mma.sync.aligned.m16n8k16.row.col.f32.bf16.bf16.f32 "
                 "{%0,%1,%2,%3}, {%4,%5,%6,%7}, {%8,%9}, {%0,%1,%2,%3};"
                 : "+f"(c[0]), "+f"(c[1]), "+f"(c[2]), "+f"(c[3])
                 : "r"(a[0]), "r"(a[1]), "r"(a[2]), "r"(a[3]),
                   "r"(b[0]), "r"(b[1]));
}
__device__ __forceinline__ void cpasync16(uint32_t dst, const void* src) {
    asm volatile("cp.async.ca.shared.global [%0], [%1], 16;" :: "r"(dst), "l"(src));
}
__device__ __forceinline__ void cp_commit() {
    asm volatile("cp.async.commit_group;" ::: "memory");
}
__device__ __forceinline__ void cp_wait1() {
    asm volatile("cp.async.wait_group 1;" ::: "memory");
}
__device__ __forceinline__ void cp_wait0() {
    asm volatile("cp.async.wait_group 0;" ::: "memory");
}
// pack two floats -> bf16x2 word (a in low half)
__device__ __forceinline__ uint32_t pkbf2(float a, float b) {
    __nv_bfloat162 t = __floats2bfloat162_rn(a, b);
    return *(uint32_t*)&t;
}

// ---------------------------------------------------------------------------
// Kernel 1: transpose features [B][Din][N] -> g_featT [B][N][Din]
// ---------------------------------------------------------------------------
__global__ void transpose_feat_kernel(const float* __restrict__ f)
{
    __shared__ float tile[32][33];
    const int b  = blockIdx.z;
    const int n0 = blockIdx.x * 32;
    const int d0 = blockIdx.y * 32;
    const int x = threadIdx.x, y = threadIdx.y;

    #pragma unroll
    for (int i = y; i < 32; i += 8)
        tile[i][x] = f[((size_t)b * DIN_ + (d0 + i)) * N_ + n0 + x];
    __syncthreads();
    #pragma unroll
    for (int i = y; i < 32; i += 8)
        g_featT[((size_t)b * N_ + (n0 + i)) * DIN_ + d0 + x] = tile[x][i];
}

// ---------------------------------------------------------------------------
// Kernel 1b: weights [Kp][Din][Dout] -> g_bhi/g_blo [Dout rows][KTOT cols]
// ---------------------------------------------------------------------------
__global__ void prep_w_kernel(const float* __restrict__ w)
{
    const int e = blockIdx.x * 256 + threadIdx.x;
    if (e >= KP_ * DIN_ * DOUT_) return;
    const int kp = e / DOUT_, o = e % DOUT_;
    const float v = w[e];
    const __nv_bfloat16 hi = __float2bfloat16(v);
    const __nv_bfloat16 lo = __float2bfloat16(v - __bfloat162float(hi));
    g_bhi[o * KTOT + kp] = hi;
    g_blo[o * KTOT + kp] = lo;
}

// ---------------------------------------------------------------------------
// Kernel 2: einsum1 on tensor cores. warp <-> point; 8 points per 256-thr CTA.
//   A = w^T [16 x 32] bf16 hi/lo (row 15 zero, shadow k -> w=0)
//   B = feat [32 x 64] bf16 hi/lo, k-major rows, ldmatrix.trans
//   v2: cooperative coalesced gather (16 lanes per 256B row, MLP=16 per lane)
//       + smem-staged coalesced epilogue (uint4 STG).
// NOTE: neighbor_indices is int32 (JAX canonicalizes int64 -> int32).
// ---------------------------------------------------------------------------
#define PTS2   8
#define FSTR   72                        // feat smem row stride (elems)
#define WSTR   40                        // w smem row stride (elems)
#define F_BYTES (K_ * FSTR * 2)          // 4608
#define W_BYTES (16 * WSTR * 2)          // 1280
#define PT_BYTES (2 * F_BYTES + 2 * W_BYTES)   // 11776
#define K2_SMEM (PTS2 * PT_BYTES)        // 94208

__global__ __launch_bounds__(256)
void kpconv_weighted_mma(const float* __restrict__ points_xyz,
                         const float* __restrict__ center_xyz,
                         const int* __restrict__ nidx,
                         const float* __restrict__ kernel_points)
{
    extern __shared__ __align__(16) char k2sm[];
    const int wpt  = threadIdx.x >> 5;   // warp id == local point id
    const int lane = threadIdx.x & 31;
    const int bm   = blockIdx.x * PTS2 + wpt;
    const int b    = bm >> 14;

    __nv_bfloat16* sFh = (__nv_bfloat16*)(k2sm + wpt * PT_BYTES);
    __nv_bfloat16* sFl = sFh + K_ * FSTR;
    __nv_bfloat16* sWh = sFl + K_ * FSTR;
    __nv_bfloat16* sWl = sWh + 16 * WSTR;

    // ---- phase 1: lane = k; coords in registers
    const int ii0 = nidx[(size_t)bm * K_ + lane];
    const bool valid = (unsigned)ii0 < (unsigned)N_;
    const int idx = valid ? ii0 : 0;
    float px = SHADOW, py = SHADOW, pz = SHADOW;
    if (valid) {
        const float* pp = points_xyz + ((size_t)b * N_ + ii0) * 3;
        px = pp[0]; py = pp[1]; pz = pp[2];
    }
    const float rx = px - center_xyz[bm * 3 + 0];
    const float ry = py - center_xyz[bm * 3 + 1];
    const float rz = pz - center_xyz[bm * 3 + 2];
    float md = sqrtf(rx * rx + ry * ry + rz * rz);
    #pragma unroll
    for (int o = 16; o; o >>= 1)
        md = fmaxf(md, __shfl_xor_sync(0xffffffffu, md, o));
    const float inv = 1.0f / (md / 2.1f + 1e-5f);

    // ---- phase 2: w[p] -> A smem [p][k=lane], bf16 hi/lo; row 15 zero
    #pragma unroll
    for (int p = 0; p < KP_; ++p) {
        const float kx = kernel_points[p * 3 + 0] * md;
        const float ky = kernel_points[p * 3 + 1] * md;
        const float kz = kernel_points[p * 3 + 2] * md;
        const float dx = rx - kx, dy = ry - ky, dz = rz - kz;
        float w = 1.0f - sqrtf(dx * dx + dy * dy + dz * dz) * inv;
        w = valid ? fmaxf(w, 0.0f) : 0.0f;
        const __nv_bfloat16 h = __float2bfloat16(w);
        sWh[p * WSTR + lane] = h;
        sWl[p * WSTR + lane] = __float2bfloat16(w - __bfloat162float(h));
    }
    sWh[15 * WSTR + lane] = __float2bfloat16(0.0f);
    sWl[15 * WSTR + lane] = __float2bfloat16(0.0f);

    // ---- phase 3: cooperative gather: 16 lanes cover one 256B feat row,
    // 2 rows per pass, 16 independent LDG.128 per lane (MLP=16, coalesced)
    {
        const int rlane = lane & 15;      // float4 slot within row
        const int rhalf = lane >> 4;      // which of the 2 rows this pass
        const float4* gfb = (const float4*)(g_featT + (size_t)b * N_ * DIN_);
        #pragma unroll
        for (int it = 0; it < 16; ++it) {
            const int k  = 2 * it + rhalf;
            const int ik = __shfl_sync(0xffffffffu, idx, k);
            const float4 f = gfb[(size_t)ik * 16 + rlane];
            const uint32_t h0 = pkbf2(f.x, f.y);
            const uint32_t h1 = pkbf2(f.z, f.w);
            const __nv_bfloat162 hh0 = *(const __nv_bfloat162*)&h0;
            const __nv_bfloat162 hh1 = *(const __nv_bfloat162*)&h1;
            const uint32_t l0 = pkbf2(f.x - __bfloat162float(hh0.x),
                                      f.y - __bfloat162float(hh0.y));
            const uint32_t l1 = pkbf2(f.z - __bfloat162float(hh1.x),
                                      f.w - __bfloat162float(hh1.y));
            *(uint2*)&sFh[k * FSTR + rlane * 4] = make_uint2(h0, h1);
            *(uint2*)&sFl[k * FSTR + rlane * 4] = make_uint2(l0, l1);
        }
    }
    __syncwarp();

    // ---- phase 4: 48 mma (2 k-chunks x 4 ldsm-groups x 2 n-tiles x 3 terms)
    float acc[8][4];
    #pragma unroll
    for (int j = 0; j < 8; ++j)
        #pragma unroll
        for (int q = 0; q < 4; ++q) acc[j][q] = 0.0f;

    const int ltile = lane >> 3, lr = lane & 7;
    const int aRow = (ltile & 1) * 8 + lr;
    const int aCol = (ltile >> 1) * 8;
    const int bRow = (ltile & 1) * 8 + lr;
    const int bCol = (ltile >> 1) * 8;

    #pragma unroll
    for (int kc = 0; kc < 2; ++kc) {
        uint32_t ah[4], al[4];
        const uint32_t aOff = (uint32_t)(aRow * WSTR + kc * 16 + aCol) * 2;
        ldsm4(ah[0], ah[1], ah[2], ah[3], smem_u32(sWh) + aOff);
        ldsm4(al[0], al[1], al[2], al[3], smem_u32(sWl) + aOff);
        #pragma unroll
        for (int g = 0; g < 4; ++g) {           // n in 16-wide groups
            const uint32_t bOff =
                (uint32_t)((kc * 16 + bRow) * FSTR + g * 16 + bCol) * 2;
            uint32_t bh[4], bl[4];
            ldsm4t(bh[0], bh[1], bh[2], bh[3], smem_u32(sFh) + bOff);
            ldsm4t(bl[0], bl[1], bl[2], bl[3], smem_u32(sFl) + bOff);
            #pragma unroll
            for (int half = 0; half < 2; ++half) {
                const int nt = 2 * g + half;
                mma16816(acc[nt], ah, bh + 2 * half);
                mma16816(acc[nt], al, bh + 2 * half);
                mma16816(acc[nt], ah, bl + 2 * half);
            }
        }
    }
    __syncwarp();

    // ---- epilogue: stage [p][64] (stride 64) into reused sFh/sFl, then
    // coalesced uint4 copy of the 960-elem row (120 uint4) to gmem.
    const int r  = lane >> 2;
    const int cb = 2 * (lane & 3);
    #pragma unroll
    for (int nt = 0; nt < 8; ++nt) {
        const int d0 = nt * 8 + cb;
        {   // p = r (0..7)
            const uint32_t h01 = pkbf2(acc[nt][0], acc[nt][1]);
            const __nv_bfloat162 hp = *(const __nv_bfloat162*)&h01;
            const uint32_t l01 = pkbf2(acc[nt][0] - __bfloat162float(hp.x),
                                       acc[nt][1] - __bfloat162float(hp.y));
            *(uint32_t*)&sFh[r * 64 + d0] = h01;
            *(uint32_t*)&sFl[r * 64 + d0] = l01;
        }
        {   // p = r+8 (8..15; row 15 staged but never copied out)
            const uint32_t h23 = pkbf2(acc[nt][2], acc[nt][3]);
            const __nv_bfloat162 hp = *(const __nv_bfloat162*)&h23;
            const uint32_t l23 = pkbf2(acc[nt][2] - __bfloat162float(hp.x),
                                       acc[nt][3] - __bfloat162float(hp.y));
            *(uint32_t*)&sFh[(r + 8) * 64 + d0] = h23;
            *(uint32_t*)&sFl[(r + 8) * 64 + d0] = l23;
        }
    }
    __syncwarp();

    {
        const uint4* eh = (const uint4*)sFh;
        const uint4* el = (const uint4*)sFl;
        uint4* wh = (uint4*)(g_whi + (size_t)bm * KTOT);
        uint4* wl = (uint4*)(g_wlo + (size_t)bm * KTOT);
        #pragma unroll
        for (int i = 0; i < 4; ++i) {
            const int e = lane + i * 32;      // 0..127, need 0..119
            if (e < 120) { wh[e] = eh[e]; wl[e] = el[e]; }
        }
    }
}

// ---------------------------------------------------------------------------
// Kernel 3: mma.sync bf16 GEMM, 3-term hi/lo split, cp.async double buffer
//   (exact R6 configuration — measured 82.0 us)
// ---------------------------------------------------------------------------
#define BK    32
#define LDS_  40                 // row stride (elements): 80B, ldsm conflict-free
#define ARR_BYTES  (128 * LDS_ * 2)          // 10240 B per array
#define STAGE_BYTES (4 * ARR_BYTES)          // Ah, Al, Bh, Bl
#define GEMM_SMEM  (2 * STAGE_BYTES)         // 81920 B

__global__ __launch_bounds__(256)
void kpconv_mma_gemm(float* __restrict__ out)
{
    extern __shared__ __align__(16) char sm[];
    const uint32_t smem_base = smem_u32(sm);

    const int tid  = threadIdx.x;
    const int wid  = tid >> 5, lane = tid & 31;
    const int wm   = wid & 3;        // warp m-offset: wm*32
    const int wn   = wid >> 2;       // warp n-offset: wn*64
    const size_t rowBase = (size_t)blockIdx.x * 128;

    auto issue_chunk = [&](int c, int stage) {
        const uint32_t sb = smem_base + stage * STAGE_BYTES;
        #pragma unroll
        for (int i = 0; i < 8; ++i) {
            const int idx = tid + i * 256;
            const int arr = idx >> 9;           // 0..3
            const int rem = idx & 511;
            const int row = rem >> 2, seg = rem & 3;
            const uint32_t dst = sb + arr * ARR_BYTES + (row * LDS_ + seg * 8) * 2;
            const __nv_bfloat16* src;
            if (arr == 0)      src = g_whi + (rowBase + row) * KTOT + c * BK + seg * 8;
            else if (arr == 1) src = g_wlo + (rowBase + row) * KTOT + c * BK + seg * 8;
            else if (arr == 2) src = g_bhi + (size_t)row * KTOT + c * BK + seg * 8;
            else               src = g_blo + (size_t)row * KTOT + c * BK + seg * 8;
            cpasync16(dst, src);
        }
        cp_commit();
    };

    float acc[2][8][4];
    #pragma unroll
    for (int i = 0; i < 2; i++)
        #pragma unroll
        for (int j = 0; j < 8; j++)
            #pragma unroll
            for (int q = 0; q < 4; q++) acc[i][j][q] = 0.0f;

    // per-lane ldmatrix row/col patterns
    const int ltile = lane >> 3, lr = lane & 7;
    const int aRow = (ltile & 1) * 8 + lr;
    const int aCol = (ltile >> 1) * 8;
    const int bRow = (ltile >> 1) * 8 + lr;
    const int bCol = (ltile & 1) * 8;

    issue_chunk(0, 0);

    for (int c = 0; c < KTOT / BK; ++c) {
        if (c + 1 < KTOT / BK) { issue_chunk(c + 1, (c + 1) & 1); cp_wait1(); }
        else                   { cp_wait0(); }
        __syncthreads();

        const uint32_t sb  = smem_base + (c & 1) * STAGE_BYTES;
        const uint32_t pAh = sb;
        const uint32_t pAl = sb + ARR_BYTES;
        const uint32_t pBh = sb + 2 * ARR_BYTES;
        const uint32_t pBl = sb + 3 * ARR_BYTES;

        #pragma unroll
        for (int kk = 0; kk < 2; ++kk) {
            const int kcol = kk * 16;
            uint32_t afh[2][4], afl[2][4];
            #pragma unroll
            for (int mt = 0; mt < 2; ++mt) {
                const int row = wm * 32 + mt * 16 + aRow;
                const int col = kcol + aCol;
                const uint32_t off = (uint32_t)(row * LDS_ + col) * 2;
                ldsm4(afh[mt][0], afh[mt][1], afh[mt][2], afh[mt][3], pAh + off);
                ldsm4(afl[mt][0], afl[mt][1], afl[mt][2], afl[mt][3], pAl + off);
            }
            #pragma unroll
            for (int g = 0; g < 4; ++g) {
                const int row = wn * 64 + g * 16 + bRow;
                const int col = kcol + bCol;
                const uint32_t off = (uint32_t)(row * LDS_ + col) * 2;
                uint32_t bh[4], bl[4];
                ldsm4(bh[0], bh[1], bh[2], bh[3], pBh + off);
                ldsm4(bl[0], bl[1], bl[2], bl[3], pBl + off);
                #pragma unroll
                for (int half = 0; half < 2; ++half) {
                    const int nt = 2 * g + half;
                    #pragma unroll
                    for (int mt = 0; mt < 2; ++mt) {
                        mma16816(acc[mt][nt], afh[mt], bh + 2 * half);
                        mma16816(acc[mt][nt], afl[mt], bh + 2 * half);
                        mma16816(acc[mt][nt], afh[mt], bl + 2 * half);
                    }
                }
            }
        }
        __syncthreads();
    }

    // epilogue: c0:(r,c) c1:(r,c+1) c2:(r+8,c) c3:(r+8,c+1)
    const int bb     = (int)(rowBase >> 14);
    const int mLocal = (int)(rowBase & 16383);
    #pragma unroll
    for (int mt = 0; mt < 2; ++mt)
        #pragma unroll
        for (int nt = 0; nt < 8; ++nt) {
            const int m0 = mLocal + wm * 32 + mt * 16 + (lane >> 2);
            const int n0 = wn * 64 + nt * 8 + 2 * (lane & 3);
            float* o0 = out + ((size_t)bb * DOUT_ + n0) * M_ + m0;
            o0[0]      = acc[mt][nt][0];
            o0[M_]     = acc[mt][nt][1];
            o0[8]      = acc[mt][nt][2];
            o0[M_ + 8] = acc[mt][nt][3];
        }
}

// ---------------------------------------------------------------------------
extern "C" void kernel_launch(void* const* d_in, const int* in_sizes, int n_in,
                              void* d_out, int out_size)
{
    // Dispatch inputs by (pairwise-distinct) element count:
    const float* points_xyz    = nullptr;
    const float* features      = nullptr;
    const float* center_xyz    = nullptr;
    const int*   neighbor_idx  = nullptr;
    const float* kernel_points = nullptr;
    const float* weights       = nullptr;

    for (int i = 0; i < n_in; i++) {
        switch (in_sizes[i]) {
            case 393216:  points_xyz    = (const float*)d_in[i]; break;
            case 8388608: features      = (const float*)d_in[i]; break;
            case 98304:   center_xyz    = (const float*)d_in[i]; break;
            case 1048576: neighbor_idx  = (const int*)d_in[i];   break;
            case 45:      kernel_points = (const float*)d_in[i]; break;
            case 122880:  weights       = (const float*)d_in[i]; break;
            default: break;
        }
    }
    float* out = (float*)d_out;

    cudaFuncSetAttribute(kpconv_mma_gemm,
                         cudaFuncAttributeMaxDynamicSharedMemorySize, GEMM_SMEM);
    cudaFuncSetAttribute(kpconv_weighted_mma,
                         cudaFuncAttributeMaxDynamicSharedMemorySize, K2_SMEM);

    dim3 g1(N_ / 32, DIN_ / 32, B_);
    transpose_feat_kernel<<<g1, dim3(32, 8)>>>(features);

    prep_w_kernel<<<(KP_ * DIN_ * DOUT_ + 255) / 256, 256>>>(weights);

    kpconv_weighted_mma<<<(B_ * M_) / PTS2, 256, K2_SMEM>>>(
        points_xyz, center_xyz, neighbor_idx, kernel_points);

    kpconv_mma_gemm<<<(B_ * M_) / 128, 256, GEMM_SMEM>>>(out);
}

// round 11
// speedup vs baseline: 1.2956x; 1.0818x over previous
#include <cuda_runtime.h>
#include <cuda_bf16.h>
#include <stdint.h>

#define B_     2
#define N_     65536
#define M_     16384
#define K_     32
#define KP_    15
#define DIN_   64
#define DOUT_  128
#define KTOT   960           // KP_*DIN_
#define SHADOW (-1000.0f)

// ---------------------------------------------------------------------------
// Scratch (__device__ globals per no-allocation rule)
// ---------------------------------------------------------------------------
__device__ float g_featT[(size_t)B_ * N_ * DIN_];                       // 33.5 MB
__device__ __align__(16) __nv_bfloat16 g_whi[(size_t)B_ * M_ * KTOT];   // 60 MB
__device__ __align__(16) __nv_bfloat16 g_wlo[(size_t)B_ * M_ * KTOT];   // 60 MB
__device__ __align__(16) __nv_bfloat16 g_bhi[DOUT_ * KTOT];             // W^T hi
__device__ __align__(16) __nv_bfloat16 g_blo[DOUT_ * KTOT];             // W^T lo

// ---------------------------------------------------------------------------
// helpers
// ---------------------------------------------------------------------------
__device__ __forceinline__ uint32_t smem_u32(const void* p) {
    uint32_t a;
    asm("{ .reg .u64 t; cvta.to.shared.u64 t, %1; cvt.u32.u64 %0, t; }"
        : "=r"(a) : "l"(p));
    return a;
}
__device__ __forceinline__ void ldsm4(uint32_t& r0, uint32_t& r1,
                                      uint32_t& r2, uint32_t& r3, uint32_t addr) {
    asm volatile("ldmatrix.sync.aligned.m8n8.x4.shared.b16 {%0,%1,%2,%3}, [%4];"
                 : "=r"(r0), "=r"(r1), "=r"(r2), "=r"(r3) : "r"(addr));
}
__device__ __forceinline__ void ldsm4t(uint32_t& r0, uint32_t& r1,
                                       uint32_t& r2, uint32_t& r3, uint32_t addr) {
    asm volatile("ldmatrix.sync.aligned.m8n8.x4.trans.shared.b16 {%0,%1,%2,%3}, [%4];"
                 : "=r"(r0), "=r"(r1), "=r"(r2), "=r"(r3) : "r"(addr));
}
__device__ __forceinline__ void mma16816(float* c, const uint32_t* a,
                                         const uint32_t* b) {
    asm volatile("mma.sync.aligned.m16n8k16.row.col.f32.bf16.bf16.f32 "
                 "{%0,%1,%2,%3}, {%4,%5,%6,%7}, {%8,%9}, {%0,%1,%2,%3};"
                 : "+f"(c[0]), "+f"(c[1]), "+f"(c[2]), "+f"(c[3])
                 : "r"(a[0]), "r"(a[1]), "r"(a[2]), "r"(a[3]),
                   "r"(b[0]), "r"(b[1]));
}
__device__ __forceinline__ void cpasync16(uint32_t dst, const void* src) {
    asm volatile("cp.async.ca.shared.global [%0], [%1], 16;" :: "r"(dst), "l"(src));
}
__device__ __forceinline__ void cp_commit() {
    asm volatile("cp.async.commit_group;" ::: "memory");
}
__device__ __forceinline__ void cp_wait1() {
    asm volatile("cp.async.wait_group 1;" ::: "memory");
}
__device__ __forceinline__ void cp_wait0() {
    asm volatile("cp.async.wait_group 0;" ::: "memory");
}
// pack two floats -> bf16x2 word (a in low half)
__device__ __forceinline__ uint32_t pkbf2(float a, float b) {
    __nv_bfloat162 t = __floats2bfloat162_rn(a, b);
    return *(uint32_t*)&t;
}

// ---------------------------------------------------------------------------
// Kernel 1: transpose features [B][Din][N] -> g_featT [B][N][Din]
// ---------------------------------------------------------------------------
__global__ void transpose_feat_kernel(const float* __restrict__ f)
{
    __shared__ float tile[32][33];
    const int b  = blockIdx.z;
    const int n0 = blockIdx.x * 32;
    const int d0 = blockIdx.y * 32;
    const int x = threadIdx.x, y = threadIdx.y;

    #pragma unroll
    for (int i = y; i < 32; i += 8)
        tile[i][x] = f[((size_t)b * DIN_ + (d0 + i)) * N_ + n0 + x];
    __syncthreads();
    #pragma unroll
    for (int i = y; i < 32; i += 8)
        g_featT[((size_t)b * N_ + (n0 + i)) * DIN_ + d0 + x] = tile[x][i];
}

// ---------------------------------------------------------------------------
// Kernel 1b: weights [Kp][Din][Dout] -> g_bhi/g_blo [Dout rows][KTOT cols]
// ---------------------------------------------------------------------------
__global__ void prep_w_kernel(const float* __restrict__ w)
{
    const int e = blockIdx.x * 256 + threadIdx.x;
    if (e >= KP_ * DIN_ * DOUT_) return;
    const int kp = e / DOUT_, o = e % DOUT_;
    const float v = w[e];
    const __nv_bfloat16 hi = __float2bfloat16(v);
    const __nv_bfloat16 lo = __float2bfloat16(v - __bfloat162float(hi));
    g_bhi[o * KTOT + kp] = hi;
    g_blo[o * KTOT + kp] = lo;
}

// ---------------------------------------------------------------------------
// Kernel 2: einsum1 on tensor cores. warp <-> point; 8 points per 256-thr CTA.
//   v3: K chunked 2x16 through a single 16-row F buffer -> per-CTA smem
//   94KB -> 57KB -> 4 CTAs/SM (32 warps) for latency hiding.
// NOTE: neighbor_indices is int32 (JAX canonicalizes int64 -> int32).
// ---------------------------------------------------------------------------
#define PTS2   8
#define FSTR   72                        // feat smem row stride (elems)
#define WSTR   40                        // w smem row stride (elems)
#define F_BYTES (16 * FSTR * 2)          // 2304 (16-row chunk buffer)
#define W_BYTES (16 * WSTR * 2)          // 1280
#define PT_BYTES (2 * F_BYTES + 2 * W_BYTES)   // 7168
#define K2_SMEM (PTS2 * PT_BYTES)        // 57344

__global__ __launch_bounds__(256)
void kpconv_weighted_mma(const float* __restrict__ points_xyz,
                         const float* __restrict__ center_xyz,
                         const int* __restrict__ nidx,
                         const float* __restrict__ kernel_points)
{
    extern __shared__ __align__(16) char k2sm[];
    const int wpt  = threadIdx.x >> 5;   // warp id == local point id
    const int lane = threadIdx.x & 31;
    const int bm   = blockIdx.x * PTS2 + wpt;
    const int b    = bm >> 14;

    __nv_bfloat16* sFh = (__nv_bfloat16*)(k2sm + wpt * PT_BYTES);
    __nv_bfloat16* sFl = sFh + 16 * FSTR;
    __nv_bfloat16* sWh = sFl + 16 * FSTR;
    __nv_bfloat16* sWl = sWh + 16 * WSTR;

    // ---- phase 1: lane = k; coords in registers
    const int ii0 = nidx[(size_t)bm * K_ + lane];
    const bool valid = (unsigned)ii0 < (unsigned)N_;
    const int idx = valid ? ii0 : 0;
    float px = SHADOW, py = SHADOW, pz = SHADOW;
    if (valid) {
        const float* pp = points_xyz + ((size_t)b * N_ + ii0) * 3;
        px = pp[0]; py = pp[1]; pz = pp[2];
    }
    const float rx = px - center_xyz[bm * 3 + 0];
    const float ry = py - center_xyz[bm * 3 + 1];
    const float rz = pz - center_xyz[bm * 3 + 2];
    float md = sqrtf(rx * rx + ry * ry + rz * rz);
    #pragma unroll
    for (int o = 16; o; o >>= 1)
        md = fmaxf(md, __shfl_xor_sync(0xffffffffu, md, o));
    const float inv = 1.0f / (md / 2.1f + 1e-5f);

    // ---- phase 2: w[p] -> A smem [p][k=lane], bf16 hi/lo; row 15 zero
    #pragma unroll
    for (int p = 0; p < KP_; ++p) {
        const float kx = kernel_points[p * 3 + 0] * md;
        const float ky = kernel_points[p * 3 + 1] * md;
        const float kz = kernel_points[p * 3 + 2] * md;
        const float dx = rx - kx, dy = ry - ky, dz = rz - kz;
        float w = 1.0f - sqrtf(dx * dx + dy * dy + dz * dz) * inv;
        w = valid ? fmaxf(w, 0.0f) : 0.0f;
        const __nv_bfloat16 h = __float2bfloat16(w);
        sWh[p * WSTR + lane] = h;
        sWl[p * WSTR + lane] = __float2bfloat16(w - __bfloat162float(h));
    }
    sWh[15 * WSTR + lane] = __float2bfloat16(0.0f);
    sWl[15 * WSTR + lane] = __float2bfloat16(0.0f);

    float acc[8][4];
    #pragma unroll
    for (int j = 0; j < 8; ++j)
        #pragma unroll
        for (int q = 0; q < 4; ++q) acc[j][q] = 0.0f;

    const int ltile = lane >> 3, lr = lane & 7;
    const int aRow = (ltile & 1) * 8 + lr;
    const int aCol = (ltile >> 1) * 8;
    const int bRow = (ltile & 1) * 8 + lr;
    const int bCol = (ltile >> 1) * 8;
    const int rlane = lane & 15;          // float4 slot within feat row
    const int rhalf = lane >> 4;          // which of 2 rows per pass
    const float4* gfb = (const float4*)(g_featT + (size_t)b * N_ * DIN_);

    #pragma unroll
    for (int kc = 0; kc < 2; ++kc) {
        // ---- gather 16 feat rows of this K-chunk (coalesced, MLP=8/lane)
        #pragma unroll
        for (int it = 0; it < 8; ++it) {
            const int kl = 2 * it + rhalf;           // local row 0..15
            const int ik = __shfl_sync(0xffffffffu, idx, kc * 16 + kl);
            const float4 f = gfb[(size_t)ik * 16 + rlane];
            const uint32_t h0 = pkbf2(f.x, f.y);
            const uint32_t h1 = pkbf2(f.z, f.w);
            const __nv_bfloat162 hh0 = *(const __nv_bfloat162*)&h0;
            const __nv_bfloat162 hh1 = *(const __nv_bfloat162*)&h1;
            const uint32_t l0 = pkbf2(f.x - __bfloat162float(hh0.x),
                                      f.y - __bfloat162float(hh0.y));
            const uint32_t l1 = pkbf2(f.z - __bfloat162float(hh1.x),
                                      f.w - __bfloat162float(hh1.y));
            *(uint2*)&sFh[kl * FSTR + rlane * 4] = make_uint2(h0, h1);
            *(uint2*)&sFl[kl * FSTR + rlane * 4] = make_uint2(l0, l1);
        }
        __syncwarp();

        // ---- A frags for this k-chunk + B frags, 24 mma
        uint32_t ah[4], al[4];
        const uint32_t aOff = (uint32_t)(aRow * WSTR + kc * 16 + aCol) * 2;
        ldsm4(ah[0], ah[1], ah[2], ah[3], smem_u32(sWh) + aOff);
        ldsm4(al[0], al[1], al[2], al[3], smem_u32(sWl) + aOff);
        #pragma unroll
        for (int g = 0; g < 4; ++g) {                // n in 16-wide groups
            const uint32_t bOff = (uint32_t)(bRow * FSTR + g * 16 + bCol) * 2;
            uint32_t bh[4], bl[4];
            ldsm4t(bh[0], bh[1], bh[2], bh[3], smem_u32(sFh) + bOff);
            ldsm4t(bl[0], bl[1], bl[2], bl[3], smem_u32(sFl) + bOff);
            #pragma unroll
            for (int half = 0; half < 2; ++half) {
                const int nt = 2 * g + half;
                mma16816(acc[nt], ah, bh + 2 * half);
                mma16816(acc[nt], al, bh + 2 * half);
                mma16816(acc[nt], ah, bl + 2 * half);
            }
        }
        __syncwarp();          // frags in regs; safe to overwrite buffer
    }

    // ---- epilogue: stage [p][64] into reused sFh/sFl (16*64 <= 16*FSTR),
    // then coalesced uint4 copy of the 960-elem row (120 uint4) to gmem.
    const int r  = lane >> 2;
    const int cb = 2 * (lane & 3);
    #pragma unroll
    for (int nt = 0; nt < 8; ++nt) {
        const int d0 = nt * 8 + cb;
        {   // p = r (0..7)
            const uint32_t h01 = pkbf2(acc[nt][0], acc[nt][1]);
            const __nv_bfloat162 hp = *(const __nv_bfloat162*)&h01;
            const uint32_t l01 = pkbf2(acc[nt][0] - __bfloat162float(hp.x),
                                       acc[nt][1] - __bfloat162float(hp.y));
            *(uint32_t*)&sFh[r * 64 + d0] = h01;
            *(uint32_t*)&sFl[r * 64 + d0] = l01;
        }
        {   // p = r+8 (8..15; row 15 staged but never copied out)
            const uint32_t h23 = pkbf2(acc[nt][2], acc[nt][3]);
            const __nv_bfloat162 hp = *(const __nv_bfloat162*)&h23;
            const uint32_t l23 = pkbf2(acc[nt][2] - __bfloat162float(hp.x),
                                       acc[nt][3] - __bfloat162float(hp.y));
            *(uint32_t*)&sFh[(r + 8) * 64 + d0] = h23;
            *(uint32_t*)&sFl[(r + 8) * 64 + d0] = l23;
        }
    }
    __syncwarp();

    {
        const uint4* eh = (const uint4*)sFh;
        const uint4* el = (const uint4*)sFl;
        uint4* wh = (uint4*)(g_whi + (size_t)bm * KTOT);
        uint4* wl = (uint4*)(g_wlo + (size_t)bm * KTOT);
        #pragma unroll
        for (int i = 0; i < 4; ++i) {
            const int e = lane + i * 32;      // 0..127, need 0..119
            if (e < 120) { wh[e] = eh[e]; wl[e] = el[e]; }
        }
    }
}

// ---------------------------------------------------------------------------
// Kernel 3: mma.sync bf16 GEMM, 3-term hi/lo split, cp.async double buffer
//   (exact R6 configuration — measured 82.0 us)
// ---------------------------------------------------------------------------
#define BK    32
#define LDS_  40                 // row stride (elements): 80B, ldsm conflict-free
#define ARR_BYTES  (128 * LDS_ * 2)          // 10240 B per array
#define STAGE_BYTES (4 * ARR_BYTES)          // Ah, Al, Bh, Bl
#define GEMM_SMEM  (2 * STAGE_BYTES)         // 81920 B

__global__ __launch_bounds__(256)
void kpconv_mma_gemm(float* __restrict__ out)
{
    extern __shared__ __align__(16) char sm[];
    const uint32_t smem_base = smem_u32(sm);

    const int tid  = threadIdx.x;
    const int wid  = tid >> 5, lane = tid & 31;
    const int wm   = wid & 3;        // warp m-offset: wm*32
    const int wn   = wid >> 2;       // warp n-offset: wn*64
    const size_t rowBase = (size_t)blockIdx.x * 128;

    auto issue_chunk = [&](int c, int stage) {
        const uint32_t sb = smem_base + stage * STAGE_BYTES;
        #pragma unroll
        for (int i = 0; i < 8; ++i) {
            const int idx = tid + i * 256;
            const int arr = idx >> 9;           // 0..3
            const int rem = idx & 511;
            const int row = rem >> 2, seg = rem & 3;
            const uint32_t dst = sb + arr * ARR_BYTES + (row * LDS_ + seg * 8) * 2;
            const __nv_bfloat16* src;
            if (arr == 0)      src = g_whi + (rowBase + row) * KTOT + c * BK + seg * 8;
            else if (arr == 1) src = g_wlo + (rowBase + row) * KTOT + c * BK + seg * 8;
            else if (arr == 2) src = g_bhi + (size_t)row * KTOT + c * BK + seg * 8;
            else               src = g_blo + (size_t)row * KTOT + c * BK + seg * 8;
            cpasync16(dst, src);
        }
        cp_commit();
    };

    float acc[2][8][4];
    #pragma unroll
    for (int i = 0; i < 2; i++)
        #pragma unroll
        for (int j = 0; j < 8; j++)
            #pragma unroll
            for (int q = 0; q < 4; q++) acc[i][j][q] = 0.0f;

    // per-lane ldmatrix row/col patterns
    const int ltile = lane >> 3, lr = lane & 7;
    const int aRow = (ltile & 1) * 8 + lr;
    const int aCol = (ltile >> 1) * 8;
    const int bRow = (ltile >> 1) * 8 + lr;
    const int bCol = (ltile & 1) * 8;

    issue_chunk(0, 0);

    for (int c = 0; c < KTOT / BK; ++c) {
        if (c + 1 < KTOT / BK) { issue_chunk(c + 1, (c + 1) & 1); cp_wait1(); }
        else                   { cp_wait0(); }
        __syncthreads();

        const uint32_t sb  = smem_base + (c & 1) * STAGE_BYTES;
        const uint32_t pAh = sb;
        const uint32_t pAl = sb + ARR_BYTES;
        const uint32_t pBh = sb + 2 * ARR_BYTES;
        const uint32_t pBl = sb + 3 * ARR_BYTES;

        #pragma unroll
        for (int kk = 0; kk < 2; ++kk) {
            const int kcol = kk * 16;
            uint32_t afh[2][4], afl[2][4];
            #pragma unroll
            for (int mt = 0; mt < 2; ++mt) {
                const int row = wm * 32 + mt * 16 + aRow;
                const int col = kcol + aCol;
                const uint32_t off = (uint32_t)(row * LDS_ + col) * 2;
                ldsm4(afh[mt][0], afh[mt][1], afh[mt][2], afh[mt][3], pAh + off);
                ldsm4(afl[mt][0], afl[mt][1], afl[mt][2], afl[mt][3], pAl + off);
            }
            #pragma unroll
            for (int g = 0; g < 4; ++g) {
                const int row = wn * 64 + g * 16 + bRow;
                const int col = kcol + bCol;
                const uint32_t off = (uint32_t)(row * LDS_ + col) * 2;
                uint32_t bh[4], bl[4];
                ldsm4(bh[0], bh[1], bh[2], bh[3], pBh + off);
                ldsm4(bl[0], bl[1], bl[2], bl[3], pBl + off);
                #pragma unroll
                for (int half = 0; half < 2; ++half) {
                    const int nt = 2 * g + half;
                    #pragma unroll
                    for (int mt = 0; mt < 2; ++mt) {
                        mma16816(acc[mt][nt], afh[mt], bh + 2 * half);
                        mma16816(acc[mt][nt], afl[mt], bh + 2 * half);
                        mma16816(acc[mt][nt], afh[mt], bl + 2 * half);
                    }
                }
            }
        }
        __syncthreads();
    }

    // epilogue: c0:(r,c) c1:(r,c+1) c2:(r+8,c) c3:(r+8,c+1)
    const int bb     = (int)(rowBase >> 14);
    const int mLocal = (int)(rowBase & 16383);
    #pragma unroll
    for (int mt = 0; mt < 2; ++mt)
        #pragma unroll
        for (int nt = 0; nt < 8; ++nt) {
            const int m0 = mLocal + wm * 32 + mt * 16 + (lane >> 2);
            const int n0 = wn * 64 + nt * 8 + 2 * (lane & 3);
            float* o0 = out + ((size_t)bb * DOUT_ + n0) * M_ + m0;
            o0[0]      = acc[mt][nt][0];
            o0[M_]     = acc[mt][nt][1];
            o0[8]      = acc[mt][nt][2];
            o0[M_ + 8] = acc[mt][nt][3];
        }
}

// ---------------------------------------------------------------------------
extern "C" void kernel_launch(void* const* d_in, const int* in_sizes, int n_in,
                              void* d_out, int out_size)
{
    // Dispatch inputs by (pairwise-distinct) element count:
    const float* points_xyz    = nullptr;
    const float* features      = nullptr;
    const float* center_xyz    = nullptr;
    const int*   neighbor_idx  = nullptr;
    const float* kernel_points = nullptr;
    const float* weights       = nullptr;

    for (int i = 0; i < n_in; i++) {
        switch (in_sizes[i]) {
            case 393216:  points_xyz    = (const float*)d_in[i]; break;
            case 8388608: features      = (const float*)d_in[i]; break;
            case 98304:   center_xyz    = (const float*)d_in[i]; break;
            case 1048576: neighbor_idx  = (const int*)d_in[i];   break;
            case 45:      kernel_points = (const float*)d_in[i]; break;
            case 122880:  weights       = (const float*)d_in[i]; break;
            default: break;
        }
    }
    float* out = (float*)d_out;

    cudaFuncSetAttribute(kpconv_mma_gemm,
                         cudaFuncAttributeMaxDynamicSharedMemorySize, GEMM_SMEM);
    cudaFuncSetAttribute(kpconv_weighted_mma,
                         cudaFuncAttributeMaxDynamicSharedMemorySize, K2_SMEM);

    dim3 g1(N_ / 32, DIN_ / 32, B_);
    transpose_feat_kernel<<<g1, dim3(32, 8)>>>(features);

    prep_w_kernel<<<(KP_ * DIN_ * DOUT_ + 255) / 256, 256>>>(weights);

    kpconv_weighted_mma<<<(B_ * M_) / PTS2, 256, K2_SMEM>>>(
        points_xyz, center_xyz, neighbor_idx, kernel_points);

    kpconv_mma_gemm<<<(B_ * M_) / 128, 256, GEMM_SMEM>>>(out);
}